// round 1
// baseline (speedup 1.0000x reference)
#include <cuda_runtime.h>

// ---------------- problem constants ----------------
#define T_STEPS 131   // 128 story + 1 query + 2 empty
#define BSZ     64
#define EMB     128
#define HID     256
#define VOCAB   32000
#define MSTL    128
#define MSEL    24
#define QL      16

// ---------------- scratch (__device__ globals; no allocs allowed) ----------
__device__ float    d_X[T_STEPS * BSZ * EMB];   // encoded inputs [t][b][e]
__device__ float    d_H[2 * HID * BSZ];         // h double buffer, k-major: [buf][k][b]
__device__ unsigned d_bar_count = 0;
__device__ unsigned d_bar_sense = 0;

// ---------------- helpers ----------------
__device__ __forceinline__ float sigf(float x) {
    return 1.0f / (1.0f + __expf(-x));
}
__device__ __forceinline__ float tanh_f(float x) {
    float a = fabsf(x);
    float e = __expf(-2.0f * a);
    float r = (1.0f - e) / (1.0f + e);
    return copysignf(r, x);
}

// ============================================================================
// Kernel 1: embedding gather + position encoding
// one warp per (b, t); lane handles e = lane*4 .. lane*4+3 (float4)
// ============================================================================
__global__ void encode_kernel(const int* __restrict__ story,
                              const int* __restrict__ query,
                              const float* __restrict__ E) {
    int wid  = blockIdx.x * 8 + (threadIdx.x >> 5);   // 0 .. 8383
    int lane = threadIdx.x & 31;
    int b = wid / T_STEPS;
    int t = wid % T_STEPS;
    int e0 = lane * 4;

    const float invE = 1.0f / (float)EMB;
    float k0 = (e0 + 1) * invE;
    float k1 = (e0 + 2) * invE;
    float k2 = (e0 + 3) * invE;
    float k3 = (e0 + 4) * invE;

    float4 acc = make_float4(0.f, 0.f, 0.f, 0.f);

    if (t < MSTL) {
        const int* toks = story + (b * MSTL + t) * MSEL;
#pragma unroll
        for (int s = 0; s < MSEL; ++s) {
            int tok = toks[s];
            float j = (s + 1) * (1.0f / 32.0f);
            float A = 1.0f - j, Bc = 1.0f - 2.0f * j;
            float4 ev = *(const float4*)(E + tok * EMB + e0);
            acc.x += ev.x * (A - k0 * Bc);
            acc.y += ev.y * (A - k1 * Bc);
            acc.z += ev.z * (A - k2 * Bc);
            acc.w += ev.w * (A - k3 * Bc);
        }
    } else if (t == MSTL) {
        const int* toks = query + b * QL;
#pragma unroll
        for (int s = 0; s < QL; ++s) {
            int tok = toks[s];
            float j = (s + 1) * (1.0f / 32.0f);
            float A = 1.0f - j, Bc = 1.0f - 2.0f * j;
            float4 ev = *(const float4*)(E + tok * EMB + e0);
            acc.x += ev.x * (A - k0 * Bc);
            acc.y += ev.y * (A - k1 * Bc);
            acc.z += ev.z * (A - k2 * Bc);
            acc.w += ev.w * (A - k3 * Bc);
        }
    }
    // t >= 129: zeros
    *(float4*)(d_X + (t * BSZ + b) * EMB + e0) = acc;
}

// ============================================================================
// Kernel 2: fused persistent LSTM recurrence
//   grid = 128 CTAs = 16 hidden-tiles (16 hidden units each) x 8 batch-tiles
//   (8 batches each). All W slices live in SMEM; one grid barrier per step.
// ============================================================================
#define RGRID 128
#define RTHREADS 256

// shared layout (in floats)
#define OFF_WHH 0                     // 64 x 257
#define OFF_WIH (64 * 257)            // 64 x 129
#define OFF_HSH (OFF_WIH + 64 * 129)  // 256 x 8 (k-major, batch fast)
#define OFF_XSH (OFF_HSH + 2048)      // 128 x 8
#define OFF_PSH (OFF_XSH + 1024)      // 4 x 64 x 8 partials
#define OFF_BSH (OFF_PSH + 2048)      // 64 bias
#define LSTM_SMEM_FLOATS (OFF_BSH + 64)
#define LSTM_SMEM_BYTES  (LSTM_SMEM_FLOATS * 4)

__global__ void __launch_bounds__(RTHREADS, 1)
lstm_kernel(const float* __restrict__ W_ih, const float* __restrict__ W_hh,
            const float* __restrict__ b_ih, const float* __restrict__ b_hh) {
    extern __shared__ float sm[];
    float* Whh_s = sm + OFF_WHH;
    float* Wih_s = sm + OFF_WIH;
    float* hsh   = sm + OFF_HSH;
    float* xsh   = sm + OFF_XSH;
    float* psh   = sm + OFF_PSH;
    float* bsh   = sm + OFF_BSH;

    const int tid = threadIdx.x;
    const int bt  = blockIdx.x & 7;   // batch tile (8 batches)
    const int ht  = blockIdx.x >> 3;  // hidden tile (16 hidden units)

    // ---- preload weight slices (once) ----
    for (int idx = tid; idx < 64 * 256; idx += RTHREADS) {
        int r = idx >> 8, k = idx & 255;
        int g = r >> 4, jj = r & 15;
        Whh_s[r * 257 + k] = W_hh[(g * 256 + ht * 16 + jj) * 256 + k];
    }
    for (int idx = tid; idx < 64 * 128; idx += RTHREADS) {
        int r = idx >> 7, k = idx & 127;
        int g = r >> 4, jj = r & 15;
        Wih_s[r * 129 + k] = W_ih[(g * 256 + ht * 16 + jj) * 128 + k];
    }
    if (tid < 64) {
        int g = tid >> 4, jj = tid & 15;
        int gr = g * 256 + ht * 16 + jj;
        bsh[tid] = b_ih[gr] + b_hh[gr];
    }

    unsigned s0 = 0;
    if (tid == 0) s0 = *(volatile unsigned*)&d_bar_sense;

    float c = 0.0f;  // cell state owned by threads tid<128 (one (jj,b) each)
    const int kc = tid >> 6;   // k-chunk 0..3
    const int r  = tid & 63;   // output gate-row within tile (g*16+jj)
    __syncthreads();

    for (int t = 0; t < T_STEPS; ++t) {
        // ---- stage x tile ----
        for (int idx = tid; idx < 1024; idx += RTHREADS) {
            int e = idx >> 3, b = idx & 7;
            xsh[idx] = d_X[(t * BSZ + bt * 8 + b) * EMB + e];
        }
        // ---- stage h tile (L1-bypassed; written by peer CTAs last step) ----
        if (t > 0) {
            const int rb = (t & 1) ^ 1;
            for (int idx = tid; idx < 2048; idx += RTHREADS) {
                int k = idx >> 3, b = idx & 7;
                hsh[idx] = __ldcg(&d_H[rb * (HID * BSZ) + k * BSZ + bt * 8 + b]);
            }
        }
        __syncthreads();

        // ---- compute: partial gates for 8 batches, one gate-row, one k-chunk
        float4 a0 = make_float4(0.f, 0.f, 0.f, 0.f);
        float4 a1 = make_float4(0.f, 0.f, 0.f, 0.f);
        {
            const float*  w  = Wih_s + r * 129 + kc * 32;
            const float4* xs = ((const float4*)xsh) + kc * 64;
#pragma unroll
            for (int k = 0; k < 32; ++k) {
                float wv = w[k];
                float4 xa = xs[2 * k], xb = xs[2 * k + 1];
                a0.x += wv * xa.x; a0.y += wv * xa.y; a0.z += wv * xa.z; a0.w += wv * xa.w;
                a1.x += wv * xb.x; a1.y += wv * xb.y; a1.z += wv * xb.z; a1.w += wv * xb.w;
            }
        }
        if (t > 0) {
            const float*  w  = Whh_s + r * 257 + kc * 64;
            const float4* hs = ((const float4*)hsh) + kc * 128;
#pragma unroll
            for (int k = 0; k < 64; ++k) {
                float wv = w[k];
                float4 ha = hs[2 * k], hb = hs[2 * k + 1];
                a0.x += wv * ha.x; a0.y += wv * ha.y; a0.z += wv * ha.z; a0.w += wv * ha.w;
                a1.x += wv * hb.x; a1.y += wv * hb.y; a1.z += wv * hb.z; a1.w += wv * hb.w;
            }
        }
        {
            float4* pp = (float4*)(psh + (kc * 64 + r) * 8);
            pp[0] = a0; pp[1] = a1;
        }
        __syncthreads();

        // ---- reduce partials + gate nonlinearities + state update ----
        if (tid < 128) {
            const int jj = tid >> 3, b = tid & 7;
            float v[4];
#pragma unroll
            for (int g = 0; g < 4; ++g) {
                int rr = g * 16 + jj;
                v[g] = psh[rr * 8 + b] + psh[(64 + rr) * 8 + b] +
                       psh[(128 + rr) * 8 + b] + psh[(192 + rr) * 8 + b] + bsh[rr];
            }
            float ig = sigf(v[0]);
            float fg = sigf(v[1]);
            float gg = tanh_f(v[2]);
            float og = sigf(v[3]);
            c = fg * c + ig * gg;
            float h = og * tanh_f(c);
            __stcg(&d_H[(t & 1) * (HID * BSZ) + (ht * 16 + jj) * BSZ + bt * 8 + b], h);
            __threadfence();
        }

        // ---- grid barrier (sense-reversing, monotonic epoch) ----
        __syncthreads();
        if (tid == 0) {
            __threadfence();
            unsigned target = s0 + (unsigned)(t + 1);
            unsigned prev = atomicAdd(&d_bar_count, 1u);
            if (prev == RGRID - 1) {
                d_bar_count = 0;
                __threadfence();
                *(volatile unsigned*)&d_bar_sense = target;
            } else {
                while (*(volatile unsigned*)&d_bar_sense != target) { }
                __threadfence();
            }
        }
        __syncthreads();
    }
}

// ============================================================================
// Kernel 3: logits = h @ lin_W.T + lin_b   ([64,256] x [256,32000])
//   125 CTAs x 256 threads; each thread owns one vocab column, acc[64] batches.
//   Final h lives in d_H buffer 0 (step 130 wrote buf 130&1 = 0), k-major.
// ============================================================================
__global__ void __launch_bounds__(256, 1)
out_kernel(const float* __restrict__ lin_W, const float* __restrict__ lin_b,
           float* __restrict__ out) {
    extern __shared__ float hsh[];  // [256][64] k-major = 64 KB
    const int tid = threadIdx.x;
    for (int idx = tid; idx < HID * BSZ; idx += 256) hsh[idx] = d_H[idx];
    __syncthreads();

    const int v = blockIdx.x * 256 + tid;
    float acc[64];
    float bb = lin_b[v];
#pragma unroll
    for (int b = 0; b < 64; ++b) acc[b] = bb;

    const float4* wp = (const float4*)(lin_W + v * HID);
    for (int kk = 0; kk < HID / 4; ++kk) {
        float4 w = wp[kk];
#pragma unroll
        for (int q = 0; q < 4; ++q) {
            float wq = (q == 0) ? w.x : (q == 1) ? w.y : (q == 2) ? w.z : w.w;
            const float4* hp = (const float4*)(hsh + (kk * 4 + q) * BSZ);
#pragma unroll
            for (int b4 = 0; b4 < 16; ++b4) {
                float4 hv = hp[b4];
                acc[b4 * 4 + 0] += wq * hv.x;
                acc[b4 * 4 + 1] += wq * hv.y;
                acc[b4 * 4 + 2] += wq * hv.z;
                acc[b4 * 4 + 3] += wq * hv.w;
            }
        }
    }
#pragma unroll
    for (int b = 0; b < 64; ++b) out[b * VOCAB + v] = acc[b];
}

// ============================================================================
// launch
// ============================================================================
extern "C" void kernel_launch(void* const* d_in, const int* in_sizes, int n_in,
                              void* d_out, int out_size) {
    const int*   story  = (const int*)d_in[0];
    const int*   query  = (const int*)d_in[1];
    const float* E      = (const float*)d_in[2];
    const float* W_ih   = (const float*)d_in[3];
    const float* W_hh   = (const float*)d_in[4];
    const float* b_ih   = (const float*)d_in[5];
    const float* b_hh   = (const float*)d_in[6];
    const float* lin_W  = (const float*)d_in[7];
    const float* lin_b  = (const float*)d_in[8];
    float*       out    = (float*)d_out;

    cudaFuncSetAttribute(lstm_kernel, cudaFuncAttributeMaxDynamicSharedMemorySize,
                         LSTM_SMEM_BYTES);
    cudaFuncSetAttribute(out_kernel, cudaFuncAttributeMaxDynamicSharedMemorySize,
                         HID * BSZ * 4);

    encode_kernel<<<(T_STEPS * BSZ) / 8, 256>>>(story, query, E);
    lstm_kernel<<<RGRID, RTHREADS, LSTM_SMEM_BYTES>>>(W_ih, W_hh, b_ih, b_hh);
    out_kernel<<<VOCAB / 256, 256, HID * BSZ * 4>>>(lin_W, lin_b, out);
}

// round 2
// speedup vs baseline: 1.2502x; 1.2502x over previous
#include <cuda_runtime.h>

// ---------------- problem constants ----------------
#define T_STEPS 131   // 128 story + 1 query + 2 empty
#define BSZ     64
#define EMB     128
#define HID     256
#define VOCAB   32000
#define MSTL    128
#define MSEL    24
#define QL      16

// ---------------- scratch (__device__ globals) ----------
__device__ float    d_X[T_STEPS * BSZ * EMB];   // encoded inputs [t][b][e]
__device__ float    d_H[2 * HID * BSZ];         // h double buffer, k-major: [buf][k][b]
__device__ unsigned d_bar_count = 0;
__device__ unsigned d_bar_sense = 0;

// ---------------- f32x2 helpers ----------------
typedef unsigned long long u64;

__device__ __forceinline__ u64 pack2(float x, float y) {
    u64 r; asm("mov.b64 %0, {%1, %2};" : "=l"(r) : "f"(x), "f"(y)); return r;
}
__device__ __forceinline__ void ffma2(u64& acc, u64 a, u64 b) {
    asm("fma.rn.f32x2 %0, %1, %2, %0;" : "+l"(acc) : "l"(a), "l"(b));
}
__device__ __forceinline__ void lds_2x64(u64& p0, u64& p1, unsigned addr) {
    asm volatile("ld.shared.v2.u64 {%0, %1}, [%2];" : "=l"(p0), "=l"(p1) : "r"(addr));
}
__device__ __forceinline__ void sts_2x64(unsigned addr, u64 p0, u64 p1) {
    asm volatile("st.shared.v2.u64 [%0], {%1, %2};" :: "r"(addr), "l"(p0), "l"(p1));
}
__device__ __forceinline__ void unpack2(u64 p, float& x, float& y) {
    asm("mov.b64 {%0, %1}, %2;" : "=f"(x), "=f"(y) : "l"(p));
}

__device__ __forceinline__ float sigf(float x) {
    return 1.0f / (1.0f + __expf(-x));
}
__device__ __forceinline__ float tanh_f(float x) {
    float a = fabsf(x);
    float e = __expf(-2.0f * a);
    float r = (1.0f - e) / (1.0f + e);
    return copysignf(r, x);
}

// ============================================================================
// Kernel 1: embedding gather + position encoding (unchanged; 11us, not critical)
// ============================================================================
__global__ void encode_kernel(const int* __restrict__ story,
                              const int* __restrict__ query,
                              const float* __restrict__ E) {
    int wid  = blockIdx.x * 8 + (threadIdx.x >> 5);
    int lane = threadIdx.x & 31;
    int b = wid / T_STEPS;
    int t = wid % T_STEPS;
    int e0 = lane * 4;

    const float invE = 1.0f / (float)EMB;
    float k0 = (e0 + 1) * invE;
    float k1 = (e0 + 2) * invE;
    float k2 = (e0 + 3) * invE;
    float k3 = (e0 + 4) * invE;

    float4 acc = make_float4(0.f, 0.f, 0.f, 0.f);

    if (t < MSTL) {
        const int* toks = story + (b * MSTL + t) * MSEL;
#pragma unroll
        for (int s = 0; s < MSEL; ++s) {
            int tok = toks[s];
            float j = (s + 1) * (1.0f / 32.0f);
            float A = 1.0f - j, Bc = 1.0f - 2.0f * j;
            float4 ev = *(const float4*)(E + tok * EMB + e0);
            acc.x += ev.x * (A - k0 * Bc);
            acc.y += ev.y * (A - k1 * Bc);
            acc.z += ev.z * (A - k2 * Bc);
            acc.w += ev.w * (A - k3 * Bc);
        }
    } else if (t == MSTL) {
        const int* toks = query + b * QL;
#pragma unroll
        for (int s = 0; s < QL; ++s) {
            int tok = toks[s];
            float j = (s + 1) * (1.0f / 32.0f);
            float A = 1.0f - j, Bc = 1.0f - 2.0f * j;
            float4 ev = *(const float4*)(E + tok * EMB + e0);
            acc.x += ev.x * (A - k0 * Bc);
            acc.y += ev.y * (A - k1 * Bc);
            acc.z += ev.z * (A - k2 * Bc);
            acc.w += ev.w * (A - k3 * Bc);
        }
    }
    *(float4*)(d_X + (t * BSZ + b) * EMB + e0) = acc;
}

// ============================================================================
// Kernel 2: fused persistent LSTM recurrence
//   128 CTAs = 16 hidden-tiles x 8 batch-tiles. Weights REGISTER-resident
//   (96 floats/thread). f32x2 packed math. Single-fence barrier. x-GEMM
//   computed before the barrier wait to hide exchange latency.
// ============================================================================
#define RGRID 128
#define RTHREADS 256

__global__ void __launch_bounds__(RTHREADS, 1)
lstm_kernel(const float* __restrict__ W_ih, const float* __restrict__ W_hh,
            const float* __restrict__ b_ih, const float* __restrict__ b_hh) {
    __shared__ __align__(16) float hsh[HID * 8];   // [k][b] b-fast
    __shared__ __align__(16) float xsh[EMB * 8];   // [e][b]
    __shared__ __align__(16) float psh[256 * 8];   // [kc*64 + r][b] partials
    __shared__ float bsh[64];

    const int tid = threadIdx.x;
    const int bt  = blockIdx.x & 7;   // batch tile (8 batches)
    const int ht  = blockIdx.x >> 3;  // hidden tile (16 hidden units)
    const int kc  = tid >> 6;         // k-chunk 0..3
    const int r   = tid & 63;         // gate-row within tile (g*16+jj)
    const int g   = r >> 4, jj = r & 15;
    const int grow = g * 256 + ht * 16 + jj;   // global gate row

    // ---- register-resident weight slices ----
    float4 wih[8];    // W_ih[grow][kc*32 .. kc*32+32)
    float4 whh[16];   // W_hh[grow][kc*64 .. kc*64+64)
    {
        const float4* p = (const float4*)(W_ih + grow * EMB + kc * 32);
#pragma unroll
        for (int q = 0; q < 8; ++q) wih[q] = p[q];
        const float4* ph = (const float4*)(W_hh + grow * HID + kc * 64);
#pragma unroll
        for (int q = 0; q < 16; ++q) whh[q] = ph[q];
    }
    if (tid < 64) {
        int gr = (tid >> 4) * 256 + ht * 16 + (tid & 15);
        bsh[tid] = b_ih[gr] + b_hh[gr];
    }

    unsigned s0 = 0;
    if (tid == 0) s0 = *(volatile unsigned*)&d_bar_sense;

    const unsigned xbase = (unsigned)__cvta_generic_to_shared(xsh) + (kc * 32) * 32;
    const unsigned hbase = (unsigned)__cvta_generic_to_shared(hsh) + (kc * 64) * 32;
    const unsigned pbase = (unsigned)__cvta_generic_to_shared(psh) + (kc * 64 + r) * 32;

    float c = 0.0f;  // cell state (threads tid<128: one (jj,b) each)
    __syncthreads();

    for (int t = 0; t < T_STEPS; ++t) {
        // ---- stage x tile (none for t>=129: x==0) ----
        if (t <= MSTL) {
            for (int idx = tid; idx < EMB * 8; idx += RTHREADS) {
                int e = idx >> 3, b = idx & 7;
                xsh[idx] = d_X[(t * BSZ + bt * 8 + b) * EMB + e];
            }
        }
        __syncthreads();

        u64 a0 = 0, a1 = 0, a2 = 0, a3 = 0;

        // ---- x-part GEMM (no h dependency; overlaps barrier latency) ----
        if (t <= MSTL) {
#pragma unroll
            for (int q = 0; q < 8; ++q) {
                float4 w4 = wih[q];
#pragma unroll
                for (int cc = 0; cc < 4; ++cc) {
                    float w = (cc == 0) ? w4.x : (cc == 1) ? w4.y : (cc == 2) ? w4.z : w4.w;
                    u64 wd = pack2(w, w);
                    u64 p0, p1, p2, p3;
                    unsigned ad = xbase + (q * 4 + cc) * 32;
                    lds_2x64(p0, p1, ad);
                    lds_2x64(p2, p3, ad + 16);
                    ffma2(a0, wd, p0); ffma2(a1, wd, p1);
                    ffma2(a2, wd, p2); ffma2(a3, wd, p3);
                }
            }
        }

        if (t > 0) {
            // ---- wait for h(t-1) publication (hidden behind x-GEMM above) ----
            if (tid == 0) {
                unsigned target = s0 + (unsigned)t;
                while ((int)(*(volatile unsigned*)&d_bar_sense - target) < 0) { }
                __threadfence();   // acquire
            }
            __syncthreads();

            // ---- stage h tile (L2, bypassing stale L1) ----
            const int rb = (t & 1) ^ 1;
            for (int idx = tid; idx < HID * 8; idx += RTHREADS) {
                int k = idx >> 3, b = idx & 7;
                hsh[idx] = __ldcg(&d_H[rb * (HID * BSZ) + k * BSZ + bt * 8 + b]);
            }
            __syncthreads();

            // ---- h-part GEMM ----
#pragma unroll
            for (int q = 0; q < 16; ++q) {
                float4 w4 = whh[q];
#pragma unroll
                for (int cc = 0; cc < 4; ++cc) {
                    float w = (cc == 0) ? w4.x : (cc == 1) ? w4.y : (cc == 2) ? w4.z : w4.w;
                    u64 wd = pack2(w, w);
                    u64 p0, p1, p2, p3;
                    unsigned ad = hbase + (q * 4 + cc) * 32;
                    lds_2x64(p0, p1, ad);
                    lds_2x64(p2, p3, ad + 16);
                    ffma2(a0, wd, p0); ffma2(a1, wd, p1);
                    ffma2(a2, wd, p2); ffma2(a3, wd, p3);
                }
            }
        }

        sts_2x64(pbase,      a0, a1);
        sts_2x64(pbase + 16, a2, a3);
        __syncthreads();

        // ---- reduce partials + gates + state update ----
        if (tid < 128) {
            const int j2 = tid >> 3, b = tid & 7;
            float v[4];
#pragma unroll
            for (int gg = 0; gg < 4; ++gg) {
                int rr = gg * 16 + j2;
                v[gg] = psh[rr * 8 + b] + psh[(64 + rr) * 8 + b] +
                        psh[(128 + rr) * 8 + b] + psh[(192 + rr) * 8 + b] + bsh[rr];
            }
            float ig = sigf(v[0]);
            float fg = sigf(v[1]);
            float gv = tanh_f(v[2]);
            float og = sigf(v[3]);
            c = fg * c + ig * gv;
            float h = og * tanh_f(c);
            __stcg(&d_H[(t & 1) * (HID * BSZ) + (ht * 16 + j2) * BSZ + bt * 8 + b], h);
        }
        __syncthreads();   // orders all h stores into tid0 (bar.sync mem semantics)

        // ---- arrive (no wait here; wait deferred to next iteration) ----
        if (tid == 0) {
            __threadfence();   // single release fence publishes CTA's h stores
            unsigned prev = atomicAdd(&d_bar_count, 1u);
            if (prev == RGRID - 1) {
                d_bar_count = 0;
                __threadfence();
                *(volatile unsigned*)&d_bar_sense = s0 + (unsigned)(t + 1);
            }
        }
        __syncthreads();   // protect psh/hsh reuse next iteration
    }
}

// ============================================================================
// Kernel 3: logits = h @ lin_W.T + lin_b  ([64,256] x [256,32000]), f32x2
//   125 CTAs x 256 threads; one vocab column/thread, 64-batch accumulators.
// ============================================================================
__global__ void __launch_bounds__(256, 1)
out_kernel(const float* __restrict__ lin_W, const float* __restrict__ lin_b,
           float* __restrict__ out) {
    extern __shared__ float hsh[];  // [256][64] k-major, 64 KB
    const int tid = threadIdx.x;
    {
        const float4* src = (const float4*)d_H;
        float4* dst = (float4*)hsh;
        for (int idx = tid; idx < HID * BSZ / 4; idx += 256) dst[idx] = src[idx];
    }
    __syncthreads();

    const int v = blockIdx.x * 256 + tid;
    const unsigned hb = (unsigned)__cvta_generic_to_shared(hsh);

    float bb = lin_b[v];
    u64 acc[32];
    u64 bp = pack2(bb, bb);
#pragma unroll
    for (int j = 0; j < 32; ++j) acc[j] = bp;

    const float4* wp = (const float4*)(lin_W + v * HID);
#pragma unroll 4
    for (int kk = 0; kk < HID / 4; ++kk) {
        float4 w4 = wp[kk];
#pragma unroll
        for (int cc = 0; cc < 4; ++cc) {
            float w = (cc == 0) ? w4.x : (cc == 1) ? w4.y : (cc == 2) ? w4.z : w4.w;
            u64 wd = pack2(w, w);
            unsigned base = hb + ((kk * 4 + cc) * BSZ) * 4;
#pragma unroll
            for (int p = 0; p < 8; ++p) {
                u64 q0, q1, q2, q3;
                lds_2x64(q0, q1, base + p * 32);
                lds_2x64(q2, q3, base + p * 32 + 16);
                ffma2(acc[p * 4 + 0], wd, q0);
                ffma2(acc[p * 4 + 1], wd, q1);
                ffma2(acc[p * 4 + 2], wd, q2);
                ffma2(acc[p * 4 + 3], wd, q3);
            }
        }
    }
#pragma unroll
    for (int j = 0; j < 32; ++j) {
        float f0, f1;
        unpack2(acc[j], f0, f1);
        out[(2 * j) * VOCAB + v]     = f0;
        out[(2 * j + 1) * VOCAB + v] = f1;
    }
}

// ============================================================================
// launch
// ============================================================================
extern "C" void kernel_launch(void* const* d_in, const int* in_sizes, int n_in,
                              void* d_out, int out_size) {
    const int*   story  = (const int*)d_in[0];
    const int*   query  = (const int*)d_in[1];
    const float* E      = (const float*)d_in[2];
    const float* W_ih   = (const float*)d_in[3];
    const float* W_hh   = (const float*)d_in[4];
    const float* b_ih   = (const float*)d_in[5];
    const float* b_hh   = (const float*)d_in[6];
    const float* lin_W  = (const float*)d_in[7];
    const float* lin_b  = (const float*)d_in[8];
    float*       out    = (float*)d_out;

    cudaFuncSetAttribute(out_kernel, cudaFuncAttributeMaxDynamicSharedMemorySize,
                         HID * BSZ * 4);

    encode_kernel<<<(T_STEPS * BSZ) / 8, 256>>>(story, query, E);
    lstm_kernel<<<RGRID, RTHREADS>>>(W_ih, W_hh, b_ih, b_hh);
    out_kernel<<<VOCAB / 256, 256, HID * BSZ * 4>>>(lin_W, lin_b, out);
}

// round 3
// speedup vs baseline: 1.4495x; 1.1594x over previous
#include <cuda_runtime.h>

// ---------------- problem constants ----------------
#define T_STEPS 131   // 128 story + 1 query + 2 empty
#define BSZ     64
#define EMB     128
#define HID     256
#define VOCAB   32000
#define MSTL    128
#define MSEL    24
#define QL      16

// ---------------- scratch ----------------
// d_X: [t][bt][e][8b]  (tile for CTA bt is contiguous 4KB), only t<=128 used
__device__ __align__(16) float d_X[129 * 8 * EMB * 8];
// d_H: [buf][bt][k][8b] (tile contiguous 8KB)
__device__ __align__(16) float d_H[2 * 8 * HID * 8];
__device__ unsigned d_bar_count[8 * 32];   // one slot per bt, 128B apart
__device__ unsigned d_bar_sense[8 * 32];

// ---------------- helpers ----------------
typedef unsigned long long u64;

__device__ __forceinline__ u64 pack2(float x, float y) {
    u64 r; asm("mov.b64 %0, {%1, %2};" : "=l"(r) : "f"(x), "f"(y)); return r;
}
__device__ __forceinline__ void ffma2(u64& acc, u64 a, u64 b) {
    asm("fma.rn.f32x2 %0, %1, %2, %0;" : "+l"(acc) : "l"(a), "l"(b));
}
__device__ __forceinline__ void lds_2x64(u64& p0, u64& p1, unsigned addr) {
    asm volatile("ld.shared.v2.u64 {%0, %1}, [%2];" : "=l"(p0), "=l"(p1) : "r"(addr));
}
__device__ __forceinline__ void sts_2x64(unsigned addr, u64 p0, u64 p1) {
    asm volatile("st.shared.v2.u64 [%0], {%1, %2};" :: "r"(addr), "l"(p0), "l"(p1));
}
__device__ __forceinline__ void unpack2(u64 p, float& x, float& y) {
    asm("mov.b64 {%0, %1}, %2;" : "=f"(x), "=f"(y) : "l"(p));
}
__device__ __forceinline__ void cp_async16(unsigned smem, const void* gptr) {
    asm volatile("cp.async.cg.shared.global [%0], [%1], 16;" :: "r"(smem), "l"(gptr));
}
__device__ __forceinline__ void cp_commit() {
    asm volatile("cp.async.commit_group;");
}
__device__ __forceinline__ void cp_wait0() {
    asm volatile("cp.async.wait_group 0;");
}

__device__ __forceinline__ float sigf(float x) {
    return 1.0f / (1.0f + __expf(-x));
}
__device__ __forceinline__ float tanh_f(float x) {
    float a = fabsf(x);
    float e = __expf(-2.0f * a);
    float r = (1.0f - e) / (1.0f + e);
    return copysignf(r, x);
}

// ============================================================================
// Kernel 1: embedding gather + position encoding -> d_X [t][bt][e][8b]
// one warp per (b, t); lane handles e = lane*4 .. lane*4+3
// ============================================================================
__global__ void encode_kernel(const int* __restrict__ story,
                              const int* __restrict__ query,
                              const float* __restrict__ E) {
    int wid  = blockIdx.x * 8 + (threadIdx.x >> 5);
    int lane = threadIdx.x & 31;
    int b = wid / T_STEPS;
    int t = wid % T_STEPS;
    if (t > MSTL) return;                  // t>=129 never read
    int e0 = lane * 4;

    const float invE = 1.0f / (float)EMB;
    float k0 = (e0 + 1) * invE;
    float k1 = (e0 + 2) * invE;
    float k2 = (e0 + 3) * invE;
    float k3 = (e0 + 4) * invE;

    float4 acc = make_float4(0.f, 0.f, 0.f, 0.f);

    if (t < MSTL) {
        const int* toks = story + (b * MSTL + t) * MSEL;
#pragma unroll
        for (int s = 0; s < MSEL; ++s) {
            int tok = toks[s];
            float j = (s + 1) * (1.0f / 32.0f);
            float A = 1.0f - j, Bc = 1.0f - 2.0f * j;
            float4 ev = *(const float4*)(E + tok * EMB + e0);
            acc.x += ev.x * (A - k0 * Bc);
            acc.y += ev.y * (A - k1 * Bc);
            acc.z += ev.z * (A - k2 * Bc);
            acc.w += ev.w * (A - k3 * Bc);
        }
    } else {  // t == MSTL: query
        const int* toks = query + b * QL;
#pragma unroll
        for (int s = 0; s < QL; ++s) {
            int tok = toks[s];
            float j = (s + 1) * (1.0f / 32.0f);
            float A = 1.0f - j, Bc = 1.0f - 2.0f * j;
            float4 ev = *(const float4*)(E + tok * EMB + e0);
            acc.x += ev.x * (A - k0 * Bc);
            acc.y += ev.y * (A - k1 * Bc);
            acc.z += ev.z * (A - k2 * Bc);
            acc.w += ev.w * (A - k3 * Bc);
        }
    }
    // scattered scalar stores into tile layout (one-time cost)
    float* dst = d_X + ((t * 8 + (b >> 3)) * EMB) * 8 + (b & 7);
    dst[(e0 + 0) * 8] = acc.x;
    dst[(e0 + 1) * 8] = acc.y;
    dst[(e0 + 2) * 8] = acc.z;
    dst[(e0 + 3) * 8] = acc.w;
}

// ============================================================================
// Kernel 2: fused persistent LSTM recurrence
//   128 CTAs = 16 ht x 8 bt, 512 threads (k-split 8). Register weights,
//   cp.async staging, double-buffered x prefetch, per-bt 16-CTA barriers.
// ============================================================================
#define RGRID 128
#define RTHREADS 512

__global__ void __launch_bounds__(RTHREADS, 1)
lstm_kernel(const float* __restrict__ W_ih, const float* __restrict__ W_hh,
            const float* __restrict__ b_ih, const float* __restrict__ b_hh) {
    __shared__ __align__(16) float xsh[2][EMB * 8];   // [buf][e][8b]
    __shared__ __align__(16) float hsh[HID * 8];      // [k][8b]
    __shared__ __align__(16) float psh[512 * 8];      // [kc*64 + r][8b]
    __shared__ float bsh[64];

    const int tid = threadIdx.x;
    const int bt  = blockIdx.x & 7;
    const int ht  = blockIdx.x >> 3;
    const int kc  = tid >> 6;          // 0..7
    const int r   = tid & 63;
    const int grow = (r >> 4) * 256 + ht * 16 + (r & 15);

    unsigned s0 = 0;
    if (tid == 0) s0 = *(volatile unsigned*)&d_bar_sense[bt * 32];

    // ---- register-resident weight slices ----
    float4 wih[4];    // W_ih[grow][kc*16 .. +16)
    float4 whh[8];    // W_hh[grow][kc*32 .. +32)
    {
        const float4* p = (const float4*)(W_ih + grow * EMB + kc * 16);
#pragma unroll
        for (int q = 0; q < 4; ++q) wih[q] = p[q];
        const float4* ph = (const float4*)(W_hh + grow * HID + kc * 32);
#pragma unroll
        for (int q = 0; q < 8; ++q) whh[q] = ph[q];
    }
    if (tid < 64) {
        int gr = (tid >> 4) * 256 + ht * 16 + (tid & 15);
        bsh[tid] = b_ih[gr] + b_hh[gr];
    }

    const unsigned xs0 = (unsigned)__cvta_generic_to_shared(&xsh[0][0]);
    const unsigned xs1 = (unsigned)__cvta_generic_to_shared(&xsh[1][0]);
    const unsigned hball = (unsigned)__cvta_generic_to_shared(hsh);
    const unsigned hbase = hball + kc * 1024;           // kc*32 rows * 32B
    const unsigned pbase = (unsigned)__cvta_generic_to_shared(psh) + tid * 32;

    // prefetch x(0)
    if (tid < 256) cp_async16(xs0 + tid * 16, d_X + bt * (EMB * 8) + tid * 4);
    cp_commit();

    float c = 0.0f;
    __syncthreads();

    for (int t = 0; t < T_STEPS; ++t) {
        u64 a0 = 0, a1 = 0, a2 = 0, a3 = 0;

        if (t <= MSTL) {
            cp_wait0();
            __syncthreads();
            // prefetch x(t+1) — lands during x-GEMM + barrier wait
            if (t < MSTL) {
                if (tid < 256)
                    cp_async16((((t + 1) & 1) ? xs1 : xs0) + tid * 16,
                               d_X + ((t + 1) * 8 + bt) * (EMB * 8) + tid * 4);
                cp_commit();
            }
            // ---- x-part GEMM (no h dependency) ----
            const unsigned xb = ((t & 1) ? xs1 : xs0) + kc * 512;
#pragma unroll
            for (int q = 0; q < 4; ++q) {
                float4 w4 = wih[q];
#pragma unroll
                for (int cc = 0; cc < 4; ++cc) {
                    float w = (cc == 0) ? w4.x : (cc == 1) ? w4.y : (cc == 2) ? w4.z : w4.w;
                    u64 wd = pack2(w, w);
                    u64 p0, p1, p2, p3;
                    unsigned ad = xb + (q * 4 + cc) * 32;
                    lds_2x64(p0, p1, ad);
                    lds_2x64(p2, p3, ad + 16);
                    ffma2(a0, wd, p0); ffma2(a1, wd, p1);
                    ffma2(a2, wd, p2); ffma2(a3, wd, p3);
                }
            }
        }

        if (t > 0) {
            // ---- wait for h(t-1) from this bt-group (16 CTAs) ----
            if (tid == 0) {
                unsigned target = s0 + (unsigned)t;
                while ((int)(*(volatile unsigned*)&d_bar_sense[bt * 32] - target) < 0) { }
                __threadfence();   // acquire
            }
            __syncthreads();
            // ---- stage h tile: 8KB contiguous, L2-direct ----
            cp_async16(hball + tid * 16,
                       d_H + (((t & 1) ^ 1) * 8 + bt) * (HID * 8) + tid * 4);
            cp_commit();
            cp_wait0();
            __syncthreads();

            // ---- h-part GEMM ----
#pragma unroll
            for (int q = 0; q < 8; ++q) {
                float4 w4 = whh[q];
#pragma unroll
                for (int cc = 0; cc < 4; ++cc) {
                    float w = (cc == 0) ? w4.x : (cc == 1) ? w4.y : (cc == 2) ? w4.z : w4.w;
                    u64 wd = pack2(w, w);
                    u64 p0, p1, p2, p3;
                    unsigned ad = hbase + (q * 4 + cc) * 32;
                    lds_2x64(p0, p1, ad);
                    lds_2x64(p2, p3, ad + 16);
                    ffma2(a0, wd, p0); ffma2(a1, wd, p1);
                    ffma2(a2, wd, p2); ffma2(a3, wd, p3);
                }
            }
        }

        sts_2x64(pbase,      a0, a1);
        sts_2x64(pbase + 16, a2, a3);
        __syncthreads();

        // ---- reduce partials + gates + state update ----
        if (tid < 128) {
            const int j2 = tid >> 3, b = tid & 7;
            float v[4];
#pragma unroll
            for (int g = 0; g < 4; ++g) {
                int rr = g * 16 + j2;
                float s = bsh[rr];
#pragma unroll
                for (int k8 = 0; k8 < 8; ++k8) s += psh[k8 * 512 + rr * 8 + b];
                v[g] = s;
            }
            float ig = sigf(v[0]);
            float fg = sigf(v[1]);
            float gv = tanh_f(v[2]);
            float og = sigf(v[3]);
            c = fg * c + ig * gv;
            float h = og * tanh_f(c);
            __stcg(&d_H[((t & 1) * 8 + bt) * (HID * 8) + (ht * 16 + j2) * 8 + b], h);
        }
        __syncthreads();   // orders h stores into tid0

        // ---- arrive on this bt-group barrier (wait deferred to next iter) ----
        if (tid == 0) {
            __threadfence();   // release: publish this CTA's h stores
            unsigned prev = atomicAdd(&d_bar_count[bt * 32], 1u);
            if (prev == 15u) {
                d_bar_count[bt * 32] = 0;
                __threadfence();
                *(volatile unsigned*)&d_bar_sense[bt * 32] = s0 + (unsigned)(t + 1);
            }
        }
        // next-iteration hazards are protected by the syncthreads at x-wait / h-wait
    }
}

// ============================================================================
// Kernel 3: logits = h @ lin_W.T + lin_b  ([64,256] x [256,32000]), f32x2
// ============================================================================
__global__ void __launch_bounds__(256, 1)
out_kernel(const float* __restrict__ lin_W, const float* __restrict__ lin_b,
           float* __restrict__ out) {
    extern __shared__ float hsh[];  // [256 k][64 b], 64 KB
    const int tid = threadIdx.x;
    {
        // d_H buf0 layout [bt][k][8b] -> hsh [k][64b]
        const float4* src = (const float4*)d_H;
        for (int idx4 = tid; idx4 < 4096; idx4 += 256) {
            int btx = idx4 >> 9, k = (idx4 >> 1) & 255, half = idx4 & 1;
            float4 v = src[idx4];
            *(float4*)(hsh + k * 64 + btx * 8 + half * 4) = v;
        }
    }
    __syncthreads();

    const int v = blockIdx.x * 256 + tid;
    const unsigned hb = (unsigned)__cvta_generic_to_shared(hsh);

    float bb = lin_b[v];
    u64 acc[32];
    u64 bp = pack2(bb, bb);
#pragma unroll
    for (int j = 0; j < 32; ++j) acc[j] = bp;

    const float4* wp = (const float4*)(lin_W + v * HID);
#pragma unroll 4
    for (int kk = 0; kk < HID / 4; ++kk) {
        float4 w4 = wp[kk];
#pragma unroll
        for (int cc = 0; cc < 4; ++cc) {
            float w = (cc == 0) ? w4.x : (cc == 1) ? w4.y : (cc == 2) ? w4.z : w4.w;
            u64 wd = pack2(w, w);
            unsigned base = hb + ((kk * 4 + cc) * BSZ) * 4;
#pragma unroll
            for (int p = 0; p < 8; ++p) {
                u64 q0, q1, q2, q3;
                lds_2x64(q0, q1, base + p * 32);
                lds_2x64(q2, q3, base + p * 32 + 16);
                ffma2(acc[p * 4 + 0], wd, q0);
                ffma2(acc[p * 4 + 1], wd, q1);
                ffma2(acc[p * 4 + 2], wd, q2);
                ffma2(acc[p * 4 + 3], wd, q3);
            }
        }
    }
#pragma unroll
    for (int j = 0; j < 32; ++j) {
        float f0, f1;
        unpack2(acc[j], f0, f1);
        out[(2 * j) * VOCAB + v]     = f0;
        out[(2 * j + 1) * VOCAB + v] = f1;
    }
}

// ============================================================================
// launch
// ============================================================================
extern "C" void kernel_launch(void* const* d_in, const int* in_sizes, int n_in,
                              void* d_out, int out_size) {
    const int*   story  = (const int*)d_in[0];
    const int*   query  = (const int*)d_in[1];
    const float* E      = (const float*)d_in[2];
    const float* W_ih   = (const float*)d_in[3];
    const float* W_hh   = (const float*)d_in[4];
    const float* b_ih   = (const float*)d_in[5];
    const float* b_hh   = (const float*)d_in[6];
    const float* lin_W  = (const float*)d_in[7];
    const float* lin_b  = (const float*)d_in[8];
    float*       out    = (float*)d_out;

    cudaFuncSetAttribute(out_kernel, cudaFuncAttributeMaxDynamicSharedMemorySize,
                         HID * BSZ * 4);

    encode_kernel<<<(T_STEPS * BSZ) / 8, 256>>>(story, query, E);
    lstm_kernel<<<RGRID, RTHREADS>>>(W_ih, W_hh, b_ih, b_hh);
    out_kernel<<<VOCAB / 256, 256, HID * BSZ * 4>>>(lin_W, lin_b, out);
}